// round 4
// baseline (speedup 1.0000x reference)
#include <cuda_runtime.h>

// Quadratic-form SH shading: out[b,p] = n4^T M(b) n4, n4=(nx,ny,nz,1).
// M is symmetric -> 10 per-batch coefficients precomputed from light[b,0..8].
//
// c0=M00, c1=M11, c2=M22  (squares)
// c3=2*M01, c4=2*M02, c5=2*M12  (cross)
// c6=2*M03, c7=2*M13, c8=2*M23  (linear)
// c9=M33  (const)

#define C1_ 0.429043f
#define C2_ 0.511664f
#define C3_ 0.743152f
#define C4_ 0.886227f
#define C5_ 0.247708f

#define NBATCH 64
#define WH (512 * 512)

__device__ float g_coef[NBATCH * 10];

__global__ void build_coef_kernel(const float* __restrict__ light) {
    int b = threadIdx.x;
    if (b >= NBATCH) return;
    const float* L = light + b * 9;
    float L0 = L[0], L1 = L[1], L2 = L[2], L3 = L[3], L4 = L[4];
    float L5 = L[5], L6 = L[6], L7 = L[7], L8 = L[8];

    float* c = g_coef + b * 10;
    c[0] = C1_ * L8;                    // M00
    c[1] = -C1_ * L8;                   // M11
    c[2] = C3_ * L6;                    // M22
    c[3] = 2.0f * C1_ * L4;             // 2*M01 (xy)
    c[4] = 2.0f * C1_ * L7;             // 2*M02 (xz)
    c[5] = 2.0f * C1_ * L5;             // 2*M12 (yz)
    c[6] = 2.0f * C2_ * L3;             // 2*M03 (x)
    c[7] = 2.0f * C2_ * L1;             // 2*M13 (y)
    c[8] = 2.0f * C2_ * L2;             // 2*M23 (z)
    c[9] = C4_ * L0 - C5_ * L6;         // M33
}

// Each thread processes 4 pixels (float4). Grid: x over WH/4/blockDim, y over batch.
__global__ void __launch_bounds__(256) shade_kernel(
    const float* __restrict__ normals,  // [B,3,512,512]
    float* __restrict__ out             // [B,1,512,512]
) {
    int b = blockIdx.y;
    int v = blockIdx.x * blockDim.x + threadIdx.x;  // float4 index within plane
    // WH/4 = 65536 float4s per plane; grid sized exactly, no bounds check needed
    // but keep one for safety:
    if (v >= WH / 4) return;

    const float* cf = g_coef + b * 10;
    float c0 = __ldg(cf + 0), c1 = __ldg(cf + 1), c2 = __ldg(cf + 2);
    float c3 = __ldg(cf + 3), c4 = __ldg(cf + 4), c5 = __ldg(cf + 5);
    float c6 = __ldg(cf + 6), c7 = __ldg(cf + 7), c8 = __ldg(cf + 8);
    float c9 = __ldg(cf + 9);

    const float4* px = (const float4*)(normals + (size_t)b * 3 * WH);
    const float4* py = (const float4*)(normals + (size_t)b * 3 * WH + WH);
    const float4* pz = (const float4*)(normals + (size_t)b * 3 * WH + 2 * WH);

    float4 x4 = __ldg(px + v);
    float4 y4 = __ldg(py + v);
    float4 z4 = __ldg(pz + v);

    float4 r;
    {
        float x = x4.x, y = y4.x, z = z4.x;
        r.x = fmaf(c0, x * x, fmaf(c1, y * y, fmaf(c2, z * z,
              fmaf(c3, x * y, fmaf(c4, x * z, fmaf(c5, y * z,
              fmaf(c6, x, fmaf(c7, y, fmaf(c8, z, c9)))))))));
    }
    {
        float x = x4.y, y = y4.y, z = z4.y;
        r.y = fmaf(c0, x * x, fmaf(c1, y * y, fmaf(c2, z * z,
              fmaf(c3, x * y, fmaf(c4, x * z, fmaf(c5, y * z,
              fmaf(c6, x, fmaf(c7, y, fmaf(c8, z, c9)))))))));
    }
    {
        float x = x4.z, y = y4.z, z = z4.z;
        r.z = fmaf(c0, x * x, fmaf(c1, y * y, fmaf(c2, z * z,
              fmaf(c3, x * y, fmaf(c4, x * z, fmaf(c5, y * z,
              fmaf(c6, x, fmaf(c7, y, fmaf(c8, z, c9)))))))));
    }
    {
        float x = x4.w, y = y4.w, z = z4.w;
        r.w = fmaf(c0, x * x, fmaf(c1, y * y, fmaf(c2, z * z,
              fmaf(c3, x * y, fmaf(c4, x * z, fmaf(c5, y * z,
              fmaf(c6, x, fmaf(c7, y, fmaf(c8, z, c9)))))))));
    }

    float4* po = (float4*)(out + (size_t)b * WH);
    po[v] = r;
}

extern "C" void kernel_launch(void* const* d_in, const int* in_sizes, int n_in,
                              void* d_out, int out_size) {
    const float* light = (const float*)d_in[0];     // [64,9]
    const float* normals = (const float*)d_in[1];   // [64,3,512,512]
    float* out = (float*)d_out;                     // [64,1,512,512]

    build_coef_kernel<<<1, NBATCH>>>(light);

    dim3 block(256);
    dim3 grid((WH / 4 + 255) / 256, NBATCH);  // (256, 64)
    shade_kernel<<<grid, block>>>(normals, out);
}

// round 5
// speedup vs baseline: 1.0402x; 1.0402x over previous
#include <cuda_runtime.h>

// Quadratic-form SH shading: out[b,p] = n4^T M(b) n4, n4=(nx,ny,nz,1).
// M symmetric -> 10 per-batch coefficients (padded to 12 for float4 loads).

#define C1_ 0.429043f
#define C2_ 0.511664f
#define C3_ 0.743152f
#define C4_ 0.886227f
#define C5_ 0.247708f

#define NBATCH 64
#define WH (512 * 512)
#define V4_PER_PLANE (WH / 4)          // 65536 float4 per plane
#define V4_PER_THREAD 2
#define THREADS 256
#define BLOCKS_X (V4_PER_PLANE / (THREADS * V4_PER_THREAD))  // 128

__device__ float4 g_coef[NBATCH * 3];  // 12 floats per batch (10 used)

__global__ void build_coef_kernel(const float* __restrict__ light) {
    int b = threadIdx.x;
    if (b >= NBATCH) return;
    const float* L = light + b * 9;
    float L0 = L[0], L1 = L[1], L2 = L[2], L3 = L[3], L4 = L[4];
    float L5 = L[5], L6 = L[6], L7 = L[7], L8 = L[8];

    float4 a, bb, cc;
    a.x = C1_ * L8;                 // c0 = M00 (x^2)
    a.y = -C1_ * L8;                // c1 = M11 (y^2)
    a.z = C3_ * L6;                 // c2 = M22 (z^2)
    a.w = 2.0f * C1_ * L4;          // c3 = 2*M01 (xy)
    bb.x = 2.0f * C1_ * L7;         // c4 = 2*M02 (xz)
    bb.y = 2.0f * C1_ * L5;         // c5 = 2*M12 (yz)
    bb.z = 2.0f * C2_ * L3;         // c6 = 2*M03 (x)
    bb.w = 2.0f * C2_ * L1;         // c7 = 2*M13 (y)
    cc.x = 2.0f * C2_ * L2;         // c8 = 2*M23 (z)
    cc.y = C4_ * L0 - C5_ * L6;     // c9 = M33 (const)
    cc.z = 0.0f;
    cc.w = 0.0f;

    g_coef[b * 3 + 0] = a;
    g_coef[b * 3 + 1] = bb;
    g_coef[b * 3 + 2] = cc;
}

__device__ __forceinline__ float quad(float x, float y, float z,
                                      float c0, float c1, float c2, float c3,
                                      float c4, float c5, float c6, float c7,
                                      float c8, float c9) {
    return fmaf(c0, x * x, fmaf(c1, y * y, fmaf(c2, z * z,
           fmaf(c3, x * y, fmaf(c4, x * z, fmaf(c5, y * z,
           fmaf(c6, x, fmaf(c7, y, fmaf(c8, z, c9)))))))));
}

__global__ void __launch_bounds__(THREADS) shade_kernel(
    const float* __restrict__ normals,  // [B,3,512,512]
    float* __restrict__ out             // [B,1,512,512]
) {
    int b = blockIdx.y;
    // Each block covers 512 contiguous float4s: thread t -> [base+t, base+t+256]
    int v0 = blockIdx.x * (THREADS * V4_PER_THREAD) + threadIdx.x;
    int v1 = v0 + THREADS;

    float4 ca = g_coef[b * 3 + 0];
    float4 cb = g_coef[b * 3 + 1];
    float4 cc = g_coef[b * 3 + 2];
    float c0 = ca.x, c1 = ca.y, c2 = ca.z, c3 = ca.w;
    float c4 = cb.x, c5 = cb.y, c6 = cb.z, c7 = cb.w;
    float c8 = cc.x, c9 = cc.y;

    const float4* px = (const float4*)(normals + (size_t)b * 3 * WH);
    const float4* py = px + V4_PER_PLANE;
    const float4* pz = py + V4_PER_PLANE;

    // Front-batch all 6 streaming loads (MLP=6)
    float4 xa = __ldg(px + v0);
    float4 xb = __ldg(px + v1);
    float4 ya = __ldg(py + v0);
    float4 yb = __ldg(py + v1);
    float4 za = __ldg(pz + v0);
    float4 zb = __ldg(pz + v1);

    float4 ra, rb;
    ra.x = quad(xa.x, ya.x, za.x, c0,c1,c2,c3,c4,c5,c6,c7,c8,c9);
    ra.y = quad(xa.y, ya.y, za.y, c0,c1,c2,c3,c4,c5,c6,c7,c8,c9);
    ra.z = quad(xa.z, ya.z, za.z, c0,c1,c2,c3,c4,c5,c6,c7,c8,c9);
    ra.w = quad(xa.w, ya.w, za.w, c0,c1,c2,c3,c4,c5,c6,c7,c8,c9);
    rb.x = quad(xb.x, yb.x, zb.x, c0,c1,c2,c3,c4,c5,c6,c7,c8,c9);
    rb.y = quad(xb.y, yb.y, zb.y, c0,c1,c2,c3,c4,c5,c6,c7,c8,c9);
    rb.z = quad(xb.z, yb.z, zb.z, c0,c1,c2,c3,c4,c5,c6,c7,c8,c9);
    rb.w = quad(xb.w, yb.w, zb.w, c0,c1,c2,c3,c4,c5,c6,c7,c8,c9);

    float4* po = (float4*)(out + (size_t)b * WH);
    po[v0] = ra;
    po[v1] = rb;
}

extern "C" void kernel_launch(void* const* d_in, const int* in_sizes, int n_in,
                              void* d_out, int out_size) {
    const float* light = (const float*)d_in[0];     // [64,9]
    const float* normals = (const float*)d_in[1];   // [64,3,512,512]
    float* out = (float*)d_out;                     // [64,1,512,512]

    build_coef_kernel<<<1, NBATCH>>>(light);

    dim3 grid(BLOCKS_X, NBATCH);  // (128, 64)
    shade_kernel<<<grid, THREADS>>>(normals, out);
}

// round 6
// speedup vs baseline: 1.0580x; 1.0171x over previous
#include <cuda_runtime.h>

// Fused quadratic-form SH shading: out[b,p] = n4^T M(b) n4, n4=(nx,ny,nz,1).
// M symmetric -> 10 coefficients computed per-thread from light[b,0..8]
// (warp-uniform loads, ~12 FLOPs; no separate pre-kernel).

#define C1_ 0.429043f
#define C2_ 0.511664f
#define C3_ 0.743152f
#define C4_ 0.886227f
#define C5_ 0.247708f

#define NBATCH 64
#define WH (512 * 512)
#define V4_PER_PLANE (WH / 4)          // 65536 float4 per plane
#define V4_PER_THREAD 4
#define THREADS 256
#define BLOCKS_X (V4_PER_PLANE / (THREADS * V4_PER_THREAD))  // 64

__device__ __forceinline__ float quad(float x, float y, float z,
                                      float c0, float c1, float c2, float c3,
                                      float c4, float c5, float c6, float c7,
                                      float c8, float c9) {
    return fmaf(c0, x * x, fmaf(c1, y * y, fmaf(c2, z * z,
           fmaf(c3, x * y, fmaf(c4, x * z, fmaf(c5, y * z,
           fmaf(c6, x, fmaf(c7, y, fmaf(c8, z, c9)))))))));
}

__global__ void __launch_bounds__(THREADS) shade_kernel(
    const float* __restrict__ light,    // [B,9]
    const float* __restrict__ normals,  // [B,3,512,512]
    float* __restrict__ out             // [B,1,512,512]
) {
    int b = blockIdx.y;

    // Coefficients from light — warp-uniform loads (L1-hit broadcast).
    const float* L = light + b * 9;
    float L0 = __ldg(L + 0), L1 = __ldg(L + 1), L2 = __ldg(L + 2);
    float L3 = __ldg(L + 3), L4 = __ldg(L + 4), L5 = __ldg(L + 5);
    float L6 = __ldg(L + 6), L7 = __ldg(L + 7), L8 = __ldg(L + 8);

    float c0 = C1_ * L8;                // M00 (x^2)
    float c1 = -C1_ * L8;               // M11 (y^2)
    float c2 = C3_ * L6;                // M22 (z^2)
    float c3 = 2.0f * C1_ * L4;         // 2*M01 (xy)
    float c4 = 2.0f * C1_ * L7;         // 2*M02 (xz)
    float c5 = 2.0f * C1_ * L5;         // 2*M12 (yz)
    float c6 = 2.0f * C2_ * L3;         // 2*M03 (x)
    float c7 = 2.0f * C2_ * L1;         // 2*M13 (y)
    float c8 = 2.0f * C2_ * L2;         // 2*M23 (z)
    float c9 = C4_ * L0 - C5_ * L6;     // M33 (const)

    // Each block covers THREADS*V4_PER_THREAD = 1024 contiguous float4s.
    int v0 = blockIdx.x * (THREADS * V4_PER_THREAD) + threadIdx.x;

    const float4* px = (const float4*)(normals + (size_t)b * 3 * WH);
    const float4* py = px + V4_PER_PLANE;
    const float4* pz = py + V4_PER_PLANE;
    float4* po = (float4*)(out + (size_t)b * WH);

    // Front-batch all 12 streaming loads (MLP=12).
    float4 xv[V4_PER_THREAD], yv[V4_PER_THREAD], zv[V4_PER_THREAD];
#pragma unroll
    for (int i = 0; i < V4_PER_THREAD; i++) xv[i] = __ldg(px + v0 + i * THREADS);
#pragma unroll
    for (int i = 0; i < V4_PER_THREAD; i++) yv[i] = __ldg(py + v0 + i * THREADS);
#pragma unroll
    for (int i = 0; i < V4_PER_THREAD; i++) zv[i] = __ldg(pz + v0 + i * THREADS);

#pragma unroll
    for (int i = 0; i < V4_PER_THREAD; i++) {
        float4 r;
        r.x = quad(xv[i].x, yv[i].x, zv[i].x, c0,c1,c2,c3,c4,c5,c6,c7,c8,c9);
        r.y = quad(xv[i].y, yv[i].y, zv[i].y, c0,c1,c2,c3,c4,c5,c6,c7,c8,c9);
        r.z = quad(xv[i].z, yv[i].z, zv[i].z, c0,c1,c2,c3,c4,c5,c6,c7,c8,c9);
        r.w = quad(xv[i].w, yv[i].w, zv[i].w, c0,c1,c2,c3,c4,c5,c6,c7,c8,c9);
        po[v0 + i * THREADS] = r;
    }
}

extern "C" void kernel_launch(void* const* d_in, const int* in_sizes, int n_in,
                              void* d_out, int out_size) {
    const float* light = (const float*)d_in[0];     // [64,9]
    const float* normals = (const float*)d_in[1];   // [64,3,512,512]
    float* out = (float*)d_out;                     // [64,1,512,512]

    dim3 grid(BLOCKS_X, NBATCH);  // (64, 64)
    shade_kernel<<<grid, THREADS>>>(light, normals, out);
}